// round 3
// baseline (speedup 1.0000x reference)
#include <cuda_runtime.h>
#include <math.h>

#define D_MODEL 1024
#define SEQ 512
#define BATCH 2
#define MTOK (BATCH*SEQ)            // 1024 tokens
#define NHEAD 16
#define DK 64
#define DFF 2048
#define NLAYER 4
#define VQN 768
#define VQD 64
#define VQCHUNKS (SEQ/VQD)          // 8
#define VQROWS (BATCH*D_MODEL*VQCHUNKS)  // 16384
#define LN_EPS 1e-6f
#define DD (D_MODEL*D_MODEL)
#define MD ((size_t)MTOK*D_MODEL)

// ------------------------- scratch (no allocation allowed) -------------------
__device__ float g_x   [MTOK*D_MODEL];
__device__ float g_x2  [MTOK*D_MODEL];
__device__ float g_qkv [3*MTOK*D_MODEL];
__device__ float g_o   [MTOK*D_MODEL];
__device__ float g_ff  [MTOK*DFF];
__device__ float g_attn[(size_t)BATCH*NHEAD*SEQ*SEQ];   // 32 MB
__device__ float g_enorm[VQN];
__device__ float g_vqerr[VQROWS];

// ------------------------- small helpers -------------------------------------
__device__ __forceinline__ float warp_sum(float v) {
    #pragma unroll
    for (int o = 16; o; o >>= 1) v += __shfl_xor_sync(0xffffffffu, v, o);
    return v;
}
__device__ __forceinline__ float warp_max(float v) {
    #pragma unroll
    for (int o = 16; o; o >>= 1) v = fmaxf(v, __shfl_xor_sync(0xffffffffu, v, o));
    return v;
}

// ------------------------- copy ----------------------------------------------
__global__ void copy_kernel(const float* __restrict__ a, float* __restrict__ b) {
    int i = blockIdx.x * blockDim.x + threadIdx.x;
    reinterpret_cast<float4*>(b)[i] = reinterpret_cast<const float4*>(a)[i];
}

// ------------------------- layernorm (ddof=1, eps on std) --------------------
// one block (256 thr) per row of 1024. ab: alpha at [0..D), beta at [D..2D)
__global__ __launch_bounds__(256) void layernorm_kernel(
    const float* __restrict__ X, float* __restrict__ Y, const float* __restrict__ ab)
{
    __shared__ float sh[8];
    size_t row = blockIdx.x;
    int tid = threadIdx.x;
    float4 v = reinterpret_cast<const float4*>(X + row * D_MODEL)[tid];
    float s = v.x + v.y + v.z + v.w;
    s = warp_sum(s);
    if ((tid & 31) == 0) sh[tid >> 5] = s;
    __syncthreads();
    float tot = sh[0]+sh[1]+sh[2]+sh[3]+sh[4]+sh[5]+sh[6]+sh[7];
    float m = tot * (1.0f / 1024.0f);
    float dx = v.x - m, dy = v.y - m, dz = v.z - m, dw = v.w - m;
    float sq = dx*dx + dy*dy + dz*dz + dw*dw;
    sq = warp_sum(sq);
    __syncthreads();
    if ((tid & 31) == 0) sh[tid >> 5] = sq;
    __syncthreads();
    float var = (sh[0]+sh[1]+sh[2]+sh[3]+sh[4]+sh[5]+sh[6]+sh[7]) * (1.0f / 1023.0f);
    float inv = 1.0f / (sqrtf(var) + LN_EPS);
    float4 al = reinterpret_cast<const float4*>(ab)[tid];
    float4 be = reinterpret_cast<const float4*>(ab + D_MODEL)[tid];
    float4 o;
    o.x = al.x * dx * inv + be.x;
    o.y = al.y * dy * inv + be.y;
    o.z = al.z * dz * inv + be.z;
    o.w = al.w * dw * inv + be.w;
    reinterpret_cast<float4*>(Y + row * D_MODEL)[tid] = o;
}

// ------------------------- SGEMM tile body -----------------------------------
// C = A(M,K) @ W(K,N) + bias (+R)(+relu). tiles: 128(M) x 64(N) x 32(K),
// 256 threads, 8x4 per thread. M/N/K all divide the tile sizes.
template<int EPI>   // 0: bias   1: bias+residual   2: bias+relu
__device__ __forceinline__ void gemm_tile(
    const float* __restrict__ A, const float* __restrict__ W,
    const float* __restrict__ bias, const float* __restrict__ R,
    float* __restrict__ C, int N, int K)
{
    __shared__ float As[32][128];
    __shared__ float Bs[32][64];
    int tid = threadIdx.x;
    int bm = blockIdx.y << 7;
    int bn = blockIdx.x << 6;
    int tx = tid & 15, ty = tid >> 4;
    float acc[8][4];
    #pragma unroll
    for (int i = 0; i < 8; i++)
        #pragma unroll
        for (int j = 0; j < 4; j++) acc[i][j] = 0.0f;

    int arow = tid >> 3;          // 0..31
    int ac4  = tid & 7;           // 0..7  (float4 column within 32-wide k tile)
    int brow = tid >> 4;          // 0..15
    int bc4  = tid & 15;          // 0..15

    for (int kt = 0; kt < K; kt += 32) {
        #pragma unroll
        for (int r = 0; r < 4; r++) {
            int row = arow + (r << 5);
            float4 va = *reinterpret_cast<const float4*>(&A[(size_t)(bm + row) * K + kt + (ac4 << 2)]);
            As[(ac4 << 2) + 0][row] = va.x;
            As[(ac4 << 2) + 1][row] = va.y;
            As[(ac4 << 2) + 2][row] = va.z;
            As[(ac4 << 2) + 3][row] = va.w;
        }
        #pragma unroll
        for (int r = 0; r < 2; r++) {
            float4 vb = *reinterpret_cast<const float4*>(
                &W[(size_t)(kt + brow + (r << 4)) * N + bn + (bc4 << 2)]);
            *reinterpret_cast<float4*>(&Bs[brow + (r << 4)][bc4 << 2]) = vb;
        }
        __syncthreads();
        #pragma unroll
        for (int k = 0; k < 32; k++) {
            float a[8], b[4];
            #pragma unroll
            for (int i = 0; i < 8; i++) a[i] = As[k][(ty << 3) + i];
            #pragma unroll
            for (int j = 0; j < 4; j++) b[j] = Bs[k][(tx << 2) + j];
            #pragma unroll
            for (int i = 0; i < 8; i++)
                #pragma unroll
                for (int j = 0; j < 4; j++)
                    acc[i][j] = fmaf(a[i], b[j], acc[i][j]);
        }
        __syncthreads();
    }
    int col = bn + (tx << 2);
    float4 bi = *reinterpret_cast<const float4*>(&bias[col]);
    #pragma unroll
    for (int i = 0; i < 8; i++) {
        int row = bm + (ty << 3) + i;
        float4 c;
        c.x = acc[i][0] + bi.x;
        c.y = acc[i][1] + bi.y;
        c.z = acc[i][2] + bi.z;
        c.w = acc[i][3] + bi.w;
        if (EPI == 1) {
            float4 r4 = *reinterpret_cast<const float4*>(&R[(size_t)row * N + col]);
            c.x += r4.x; c.y += r4.y; c.z += r4.z; c.w += r4.w;
        }
        if (EPI == 2) {
            c.x = fmaxf(c.x, 0.0f); c.y = fmaxf(c.y, 0.0f);
            c.z = fmaxf(c.z, 0.0f); c.w = fmaxf(c.w, 0.0f);
        }
        *reinterpret_cast<float4*>(&C[(size_t)row * N + col]) = c;
    }
}

template<int EPI>
__global__ __launch_bounds__(256) void sgemm_kernel(
    const float* __restrict__ A, const float* __restrict__ W,
    const float* __restrict__ bias, const float* __restrict__ R,
    float* __restrict__ C, int N, int K)
{
    gemm_tile<EPI>(A, W, bias, R, C, N, K);
}

// Fused Q/K/V projection: gridDim.z = 3 selects the matrix. Q reads Aq;
// K and V read Akv (equals Aq for self-attn, vq_output for cross-attn).
__global__ __launch_bounds__(256) void sgemm_qkv_kernel(
    const float* __restrict__ Aq, const float* __restrict__ Akv,
    const float* __restrict__ W, const float* __restrict__ bias,
    float* __restrict__ C)
{
    int z = blockIdx.z;
    gemm_tile<0>((z == 0) ? Aq : Akv, W + (size_t)z * DD, bias + z * D_MODEL,
                 nullptr, C + (size_t)z * MD, D_MODEL, D_MODEL);
}

// ------------------------- attention: scores = Qh @ Kh^T * 0.125 -------------
// grid (SEQ/64, SEQ/64, B*H), 256 threads, 64x64 tile, dk=64 in one pass.
__global__ __launch_bounds__(256) void attn_scores_kernel(
    const float* __restrict__ Q, const float* __restrict__ Km, float* __restrict__ P)
{
    __shared__ float Qs[64][68];   // [kdim][qrow]
    __shared__ float Ks[64][68];   // [kdim][krow]
    int bh = blockIdx.z;
    int b = bh >> 4, h = bh & 15;
    int q0 = blockIdx.y << 6, k0 = blockIdx.x << 6;
    int tid = threadIdx.x;
    int lrow = tid >> 2;
    int lk0  = (tid & 3) << 4;
    const float* qb = Q + (size_t)(b * SEQ + q0 + lrow) * D_MODEL + h * DK + lk0;
    const float* kb = Km + (size_t)(b * SEQ + k0 + lrow) * D_MODEL + h * DK + lk0;
    #pragma unroll
    for (int u = 0; u < 4; u++) {
        float4 qv = *reinterpret_cast<const float4*>(qb + (u << 2));
        float4 kv = *reinterpret_cast<const float4*>(kb + (u << 2));
        int kd = lk0 + (u << 2);
        Qs[kd+0][lrow]=qv.x; Qs[kd+1][lrow]=qv.y; Qs[kd+2][lrow]=qv.z; Qs[kd+3][lrow]=qv.w;
        Ks[kd+0][lrow]=kv.x; Ks[kd+1][lrow]=kv.y; Ks[kd+2][lrow]=kv.z; Ks[kd+3][lrow]=kv.w;
    }
    __syncthreads();
    int tx = tid & 15, ty = tid >> 4;
    float acc[4][4];
    #pragma unroll
    for (int i = 0; i < 4; i++)
        #pragma unroll
        for (int j = 0; j < 4; j++) acc[i][j] = 0.0f;
    #pragma unroll 8
    for (int k = 0; k < 64; k++) {
        float4 a = *reinterpret_cast<const float4*>(&Qs[k][ty << 2]);
        float4 bb = *reinterpret_cast<const float4*>(&Ks[k][tx << 2]);
        float av[4] = {a.x, a.y, a.z, a.w};
        float bv[4] = {bb.x, bb.y, bb.z, bb.w};
        #pragma unroll
        for (int i = 0; i < 4; i++)
            #pragma unroll
            for (int j = 0; j < 4; j++)
                acc[i][j] = fmaf(av[i], bv[j], acc[i][j]);
    }
    #pragma unroll
    for (int i = 0; i < 4; i++) {
        float4 r;
        r.x = acc[i][0] * 0.125f; r.y = acc[i][1] * 0.125f;
        r.z = acc[i][2] * 0.125f; r.w = acc[i][3] * 0.125f;
        *reinterpret_cast<float4*>(
            &P[((size_t)bh * SEQ + q0 + (ty << 2) + i) * SEQ + k0 + (tx << 2)]) = r;
    }
}

// ------------------------- softmax (rows of 512) ------------------------------
__global__ __launch_bounds__(128) void softmax_kernel(float* __restrict__ P) {
    __shared__ float sh[4];
    size_t row = blockIdx.x;
    float* p = P + row * SEQ;
    int tid = threadIdx.x;
    float v0 = p[tid], v1 = p[tid + 128], v2 = p[tid + 256], v3 = p[tid + 384];
    float m = fmaxf(fmaxf(v0, v1), fmaxf(v2, v3));
    m = warp_max(m);
    if ((tid & 31) == 0) sh[tid >> 5] = m;
    __syncthreads();
    float mm = fmaxf(fmaxf(sh[0], sh[1]), fmaxf(sh[2], sh[3]));
    v0 = expf(v0 - mm); v1 = expf(v1 - mm); v2 = expf(v2 - mm); v3 = expf(v3 - mm);
    float s = v0 + v1 + v2 + v3;
    s = warp_sum(s);
    __syncthreads();
    if ((tid & 31) == 0) sh[tid >> 5] = s;
    __syncthreads();
    float inv = 1.0f / (sh[0] + sh[1] + sh[2] + sh[3]);
    p[tid] = v0 * inv; p[tid + 128] = v1 * inv; p[tid + 256] = v2 * inv; p[tid + 384] = v3 * inv;
}

// ------------------------- attention: O = P @ Vh ------------------------------
// grid (1, SEQ/64, B*H), 64 q-rows x 64 head-dims per block, k tiles of 64.
__global__ __launch_bounds__(256) void attn_av_kernel(
    const float* __restrict__ P, const float* __restrict__ V, float* __restrict__ O)
{
    __shared__ float Ps[64][68];   // [krow][qrow]
    __shared__ float Vs[64][68];   // [krow][dim]
    int bh = blockIdx.z;
    int b = bh >> 4, h = bh & 15;
    int q0 = blockIdx.y << 6;
    int tid = threadIdx.x;
    int lrow = tid >> 2;
    int lc0  = (tid & 3) << 4;
    int tx = tid & 15, ty = tid >> 4;
    float acc[4][4];
    #pragma unroll
    for (int i = 0; i < 4; i++)
        #pragma unroll
        for (int j = 0; j < 4; j++) acc[i][j] = 0.0f;

    for (int kt = 0; kt < SEQ; kt += 64) {
        const float* pb = P + ((size_t)bh * SEQ + q0 + lrow) * SEQ + kt + lc0;
        const float* vb = V + (size_t)(b * SEQ + kt + lrow) * D_MODEL + h * DK + lc0;
        #pragma unroll
        for (int u = 0; u < 4; u++) {
            float4 pv = *reinterpret_cast<const float4*>(pb + (u << 2));
            int kc = lc0 + (u << 2);
            Ps[kc+0][lrow]=pv.x; Ps[kc+1][lrow]=pv.y; Ps[kc+2][lrow]=pv.z; Ps[kc+3][lrow]=pv.w;
            float4 vv = *reinterpret_cast<const float4*>(vb + (u << 2));
            *reinterpret_cast<float4*>(&Vs[lrow][lc0 + (u << 2)]) = vv;
        }
        __syncthreads();
        #pragma unroll 8
        for (int k = 0; k < 64; k++) {
            float4 a = *reinterpret_cast<const float4*>(&Ps[k][ty << 2]);
            float4 bb = *reinterpret_cast<const float4*>(&Vs[k][tx << 2]);
            float av[4] = {a.x, a.y, a.z, a.w};
            float bv[4] = {bb.x, bb.y, bb.z, bb.w};
            #pragma unroll
            for (int i = 0; i < 4; i++)
                #pragma unroll
                for (int j = 0; j < 4; j++)
                    acc[i][j] = fmaf(av[i], bv[j], acc[i][j]);
        }
        __syncthreads();
    }
    #pragma unroll
    for (int i = 0; i < 4; i++) {
        float4 r = make_float4(acc[i][0], acc[i][1], acc[i][2], acc[i][3]);
        *reinterpret_cast<float4*>(
            &O[(size_t)(b * SEQ + q0 + (ty << 2) + i) * D_MODEL + h * DK + (tx << 2)]) = r;
    }
}

// ------------------------- VQ -------------------------------------------------
__global__ void enorm_kernel(const float* __restrict__ emb, float* __restrict__ en) {
    int j = blockIdx.x * blockDim.x + threadIdx.x;
    if (j < VQN) {
        float s = 0.0f;
        #pragma unroll 16
        for (int t = 0; t < VQD; t++) { float e = emb[j * VQD + t]; s = fmaf(e, e, s); }
        en[j] = s;
    }
}

// one block (128 thr) per flat row: (b,d,chunk) -> 64 consecutive tokens of dim d
__global__ __launch_bounds__(128) void vq_kernel(
    const float* __restrict__ E, const float* __restrict__ emb,
    const float* __restrict__ en, float* __restrict__ VQ, float* __restrict__ err)
{
    __shared__ float f[VQD];
    __shared__ float sval[128];
    __shared__ int   sidx[128];
    int row = blockIdx.x;
    int chunk = row % VQCHUNKS;
    int bd = row / VQCHUNKS;
    int d = bd % D_MODEL, b = bd / D_MODEL;
    int s0 = chunk * VQD;
    int tid = threadIdx.x;
    if (tid < VQD) f[tid] = E[(size_t)(b * SEQ + s0 + tid) * D_MODEL + d];
    __syncthreads();

    float best = INFINITY; int bidx = 0x7fffffff;
    for (int j = tid; j < VQN; j += 128) {
        const float* e = emb + (size_t)j * VQD;
        float dot = 0.0f;
        #pragma unroll 16
        for (int t = 0; t < VQD; t++) dot = fmaf(f[t], e[t], dot);
        float dist = en[j] - 2.0f * dot;     // + ||f||^2 constant: argmin-equivalent
        if (dist < best) { best = dist; bidx = j; }
    }
    sval[tid] = best; sidx[tid] = bidx;
    __syncthreads();
    #pragma unroll
    for (int s = 64; s > 0; s >>= 1) {
        if (tid < s) {
            float ov = sval[tid + s]; int oi = sidx[tid + s];
            if (ov < sval[tid] || (ov == sval[tid] && oi < sidx[tid])) {
                sval[tid] = ov; sidx[tid] = oi;
            }
        }
        __syncthreads();
    }
    int win = sidx[0];
    if (tid < VQD) {
        float e = emb[(size_t)win * VQD + tid];
        VQ[(size_t)(b * SEQ + s0 + tid) * D_MODEL + d] = e;
        float df = e - f[tid];
        float s2 = warp_sum(df * df);
        if ((tid & 31) == 0) sval[tid >> 5] = s2;
    }
    __syncthreads();
    if (tid == 0) err[row] = sval[0] + sval[1];
}

__global__ void loss_kernel(const float* __restrict__ err, float* __restrict__ out) {
    __shared__ float sh[8];
    int tid = threadIdx.x;
    float s = 0.0f;
    for (int i = tid; i < VQROWS; i += 256) s += err[i];
    s = warp_sum(s);
    if ((tid & 31) == 0) sh[tid >> 5] = s;
    __syncthreads();
    if (tid == 0) {
        float tot = sh[0]+sh[1]+sh[2]+sh[3]+sh[4]+sh[5]+sh[6]+sh[7];
        out[0] = 0.25f * tot / (float)(BATCH * D_MODEL * SEQ);
    }
}

// ------------------------- host-side orchestration ----------------------------
struct Scratch {
    float *x, *x2, *qkv, *o, *ff, *attn, *enorm, *vqerr;
};
static Scratch get_scratch() {
    static Scratch s;
    static bool init = false;
    if (!init) {
        cudaGetSymbolAddress((void**)&s.x,     g_x);
        cudaGetSymbolAddress((void**)&s.x2,    g_x2);
        cudaGetSymbolAddress((void**)&s.qkv,   g_qkv);
        cudaGetSymbolAddress((void**)&s.o,     g_o);
        cudaGetSymbolAddress((void**)&s.ff,    g_ff);
        cudaGetSymbolAddress((void**)&s.attn,  g_attn);
        cudaGetSymbolAddress((void**)&s.enorm, g_enorm);
        cudaGetSymbolAddress((void**)&s.vqerr, g_vqerr);
        init = true;
    }
    return s;
}

static void launch_gemm(int epi, const float* A, const float* W, const float* bias,
                        const float* R, float* C, int N, int K)
{
    dim3 grid(N / 64, MTOK / 128), block(256);
    if (epi == 0)      sgemm_kernel<0><<<grid, block>>>(A, W, bias, R, C, N, K);
    else if (epi == 1) sgemm_kernel<1><<<grid, block>>>(A, W, bias, R, C, N, K);
    else               sgemm_kernel<2><<<grid, block>>>(A, W, bias, R, C, N, K);
}

static void run_mha(const float* xq, const float* xkv, const float* w, const float* bias,
                    float* xres, const Scratch& s)
{
    const float* q = s.qkv;
    const float* k = s.qkv + MD;
    const float* v = s.qkv + 2 * MD;
    sgemm_qkv_kernel<<<dim3(D_MODEL/64, MTOK/128, 3), 256>>>(xq, xkv, w, bias, s.qkv);
    attn_scores_kernel<<<dim3(SEQ/64, SEQ/64, BATCH*NHEAD), 256>>>(q, k, s.attn);
    softmax_kernel<<<BATCH*NHEAD*SEQ, 128>>>(s.attn);
    attn_av_kernel<<<dim3(1, SEQ/64, BATCH*NHEAD), 256>>>(s.attn, v, s.o);
    launch_gemm(1, s.o, w + 3*DD, bias + 3*D_MODEL, xres, xres, D_MODEL, D_MODEL);
}

extern "C" void kernel_launch(void* const* d_in, const int* in_sizes, int n_in,
                              void* d_out, int out_size)
{
    const float* src        = (const float*)d_in[0];
    const float* trg        = (const float*)d_in[1];
    const float* enc_ln     = (const float*)d_in[2];
    const float* enc_attn_w = (const float*)d_in[3];
    const float* enc_attn_b = (const float*)d_in[4];
    const float* enc_ff_w1  = (const float*)d_in[5];
    const float* enc_ff_b1  = (const float*)d_in[6];
    const float* enc_ff_w2  = (const float*)d_in[7];
    const float* enc_ff_b2  = (const float*)d_in[8];
    const float* enc_fnorm  = (const float*)d_in[9];
    const float* dec_ln     = (const float*)d_in[10];
    const float* dec_a1_w   = (const float*)d_in[11];
    const float* dec_a1_b   = (const float*)d_in[12];
    const float* dec_a2_w   = (const float*)d_in[13];
    const float* dec_a2_b   = (const float*)d_in[14];
    const float* dec_ff_w1  = (const float*)d_in[15];
    const float* dec_ff_b1  = (const float*)d_in[16];
    const float* dec_ff_w2  = (const float*)d_in[17];
    const float* dec_ff_b2  = (const float*)d_in[18];
    const float* dec_fnorm  = (const float*)d_in[19];
    const float* out_w      = (const float*)d_in[20];
    const float* out_b      = (const float*)d_in[21];
    const float* vq_emb     = (const float*)d_in[22];

    float* out      = (float*)d_out;
    float* out_main = out;
    float* out_e    = out + MD;
    float* out_vq   = out + 2 * MD;
    float* out_loss = out + 3 * MD;

    Scratch s = get_scratch();

    // ---------------- encoder ----------------
    copy_kernel<<<MTOK * D_MODEL / (256 * 4), 256>>>(src, s.x);
    for (int l = 0; l < NLAYER; l++) {
        layernorm_kernel<<<MTOK, 256>>>(s.x, s.x2, enc_ln + (size_t)((l*2 + 0) * 2) * D_MODEL);
        run_mha(s.x2, s.x2, enc_attn_w + (size_t)l*4*DD, enc_attn_b + (size_t)l*4*D_MODEL,
                s.x, s);
        layernorm_kernel<<<MTOK, 256>>>(s.x, s.x2, enc_ln + (size_t)((l*2 + 1) * 2) * D_MODEL);
        launch_gemm(2, s.x2, enc_ff_w1 + (size_t)l*D_MODEL*DFF, enc_ff_b1 + (size_t)l*DFF,
                    nullptr, s.ff, DFF, D_MODEL);
        launch_gemm(1, s.ff, enc_ff_w2 + (size_t)l*DFF*D_MODEL, enc_ff_b2 + (size_t)l*D_MODEL,
                    s.x, s.x, D_MODEL, DFF);
    }
    layernorm_kernel<<<MTOK, 256>>>(s.x, out_e, enc_fnorm);

    // ---------------- VQ ----------------
    enorm_kernel<<<(VQN + 127) / 128, 128>>>(vq_emb, s.enorm);
    vq_kernel<<<VQROWS, 128>>>(out_e, vq_emb, s.enorm, out_vq, s.vqerr);
    loss_kernel<<<1, 256>>>(s.vqerr, out_loss);

    // ---------------- decoder ----------------
    copy_kernel<<<MTOK * D_MODEL / (256 * 4), 256>>>(trg, s.x);
    for (int l = 0; l < NLAYER; l++) {
        layernorm_kernel<<<MTOK, 256>>>(s.x, s.x2, dec_ln + (size_t)((l*3 + 0) * 2) * D_MODEL);
        run_mha(s.x2, s.x2, dec_a1_w + (size_t)l*4*DD, dec_a1_b + (size_t)l*4*D_MODEL,
                s.x, s);
        layernorm_kernel<<<MTOK, 256>>>(s.x, s.x2, dec_ln + (size_t)((l*3 + 1) * 2) * D_MODEL);
        run_mha(s.x2, out_vq, dec_a2_w + (size_t)l*4*DD, dec_a2_b + (size_t)l*4*D_MODEL,
                s.x, s);
        layernorm_kernel<<<MTOK, 256>>>(s.x, s.x2, dec_ln + (size_t)((l*3 + 2) * 2) * D_MODEL);
        launch_gemm(2, s.x2, dec_ff_w1 + (size_t)l*D_MODEL*DFF, dec_ff_b1 + (size_t)l*DFF,
                    nullptr, s.ff, DFF, D_MODEL);
        launch_gemm(1, s.ff, dec_ff_w2 + (size_t)l*DFF*D_MODEL, dec_ff_b2 + (size_t)l*D_MODEL,
                    s.x, s.x, D_MODEL, DFF);
    }
    layernorm_kernel<<<MTOK, 256>>>(s.x, s.x2, dec_fnorm);
    launch_gemm(0, s.x2, out_w, out_b, nullptr, out_main, D_MODEL, D_MODEL);
}

// round 4
// speedup vs baseline: 1.0340x; 1.0340x over previous
#include <cuda_runtime.h>
#include <math.h>

#define D_MODEL 1024
#define SEQ 512
#define BATCH 2
#define MTOK (BATCH*SEQ)            // 1024 tokens
#define NHEAD 16
#define DK 64
#define DFF 2048
#define NLAYER 4
#define VQN 768
#define VQD 64
#define VQCHUNKS (SEQ/VQD)          // 8
#define VQROWS (BATCH*D_MODEL*VQCHUNKS)  // 16384
#define LN_EPS 1e-6f
#define DD (D_MODEL*D_MODEL)
#define MD ((size_t)MTOK*D_MODEL)

// ------------------------- scratch (no allocation allowed) -------------------
__device__ float g_x   [MTOK*D_MODEL];
__device__ float g_x2  [MTOK*D_MODEL];
__device__ float g_qkv [3*MTOK*D_MODEL];
__device__ float g_o   [MTOK*D_MODEL];
__device__ float g_ff  [MTOK*DFF];
__device__ float g_attn[(size_t)BATCH*NHEAD*SEQ*SEQ];   // 32 MB
__device__ float g_enorm[VQN];
__device__ float g_vqerr[VQROWS];

// ------------------------- small helpers -------------------------------------
__device__ __forceinline__ float warp_sum(float v) {
    #pragma unroll
    for (int o = 16; o; o >>= 1) v += __shfl_xor_sync(0xffffffffu, v, o);
    return v;
}
__device__ __forceinline__ float warp_max(float v) {
    #pragma unroll
    for (int o = 16; o; o >>= 1) v = fmaxf(v, __shfl_xor_sync(0xffffffffu, v, o));
    return v;
}

// ------------------------- copy ----------------------------------------------
__global__ void copy_kernel(const float* __restrict__ a, float* __restrict__ b) {
    int i = blockIdx.x * blockDim.x + threadIdx.x;
    reinterpret_cast<float4*>(b)[i] = reinterpret_cast<const float4*>(a)[i];
}

// ------------------------- layernorm (ddof=1, eps on std) --------------------
__global__ __launch_bounds__(256) void layernorm_kernel(
    const float* __restrict__ X, float* __restrict__ Y, const float* __restrict__ ab)
{
    __shared__ float sh[8];
    size_t row = blockIdx.x;
    int tid = threadIdx.x;
    float4 v = reinterpret_cast<const float4*>(X + row * D_MODEL)[tid];
    float s = v.x + v.y + v.z + v.w;
    s = warp_sum(s);
    if ((tid & 31) == 0) sh[tid >> 5] = s;
    __syncthreads();
    float tot = sh[0]+sh[1]+sh[2]+sh[3]+sh[4]+sh[5]+sh[6]+sh[7];
    float m = tot * (1.0f / 1024.0f);
    float dx = v.x - m, dy = v.y - m, dz = v.z - m, dw = v.w - m;
    float sq = dx*dx + dy*dy + dz*dz + dw*dw;
    sq = warp_sum(sq);
    __syncthreads();
    if ((tid & 31) == 0) sh[tid >> 5] = sq;
    __syncthreads();
    float var = (sh[0]+sh[1]+sh[2]+sh[3]+sh[4]+sh[5]+sh[6]+sh[7]) * (1.0f / 1023.0f);
    float inv = 1.0f / (sqrtf(var) + LN_EPS);
    float4 al = reinterpret_cast<const float4*>(ab)[tid];
    float4 be = reinterpret_cast<const float4*>(ab + D_MODEL)[tid];
    float4 o;
    o.x = al.x * dx * inv + be.x;
    o.y = al.y * dy * inv + be.y;
    o.z = al.z * dz * inv + be.z;
    o.w = al.w * dw * inv + be.w;
    reinterpret_cast<float4*>(Y + row * D_MODEL)[tid] = o;
}

// ------------------------- SGEMM tile body (v2) -------------------------------
// C = A(M,K) @ W(K,N) + bias (+R)(+relu).
// Block tile: 128(M) x 64(N) x 32(K). 128 threads, 8x8 per thread.
// Double-buffered smem, register-staged global prefetch.
template<int EPI>   // 0: bias   1: bias+residual   2: bias+relu
__device__ __forceinline__ void gemm_tile(
    const float* __restrict__ A, const float* __restrict__ W,
    const float* __restrict__ bias, const float* __restrict__ R,
    float* __restrict__ C, int N, int K)
{
    __shared__ __align__(16) float As[2][32][128];   // [stage][k][m]  32 KB
    __shared__ __align__(16) float Bs[2][32][64];    // [stage][k][n]  16 KB
    int tid = threadIdx.x;
    int bm = blockIdx.y << 7;
    int bn = blockIdx.x << 6;
    int tx = tid & 7;            // 0..7  -> 8 output cols
    int ty = tid >> 3;           // 0..15 -> 8 output rows
    int bkr = tid >> 4;          // 0..7  B k-row base
    int bc4 = (tid & 15) << 2;   // B col (floats)

    const float* Arow = A + (size_t)(bm + tid) * K;   // one A row per thread

    float acc[8][8];
    #pragma unroll
    for (int i = 0; i < 8; i++)
        #pragma unroll
        for (int j = 0; j < 8; j++) acc[i][j] = 0.0f;

    float4 ar[8], br[4];

    // ---- prologue: load tile 0 ----
    #pragma unroll
    for (int j = 0; j < 8; j++)
        ar[j] = *reinterpret_cast<const float4*>(Arow + (j << 2));
    #pragma unroll
    for (int p = 0; p < 4; p++)
        br[p] = *reinterpret_cast<const float4*>(&W[(size_t)(bkr + (p << 3)) * N + bn + bc4]);
    #pragma unroll
    for (int j = 0; j < 8; j++) {
        As[0][(j << 2) + 0][tid] = ar[j].x;
        As[0][(j << 2) + 1][tid] = ar[j].y;
        As[0][(j << 2) + 2][tid] = ar[j].z;
        As[0][(j << 2) + 3][tid] = ar[j].w;
    }
    #pragma unroll
    for (int p = 0; p < 4; p++)
        *reinterpret_cast<float4*>(&Bs[0][bkr + (p << 3)][bc4]) = br[p];
    __syncthreads();

    int nt = K >> 5;
    for (int t = 0; t < nt; t++) {
        int cur = t & 1, nxt = cur ^ 1;
        if (t + 1 < nt) {
            int kt = (t + 1) << 5;
            #pragma unroll
            for (int j = 0; j < 8; j++)
                ar[j] = *reinterpret_cast<const float4*>(Arow + kt + (j << 2));
            #pragma unroll
            for (int p = 0; p < 4; p++)
                br[p] = *reinterpret_cast<const float4*>(
                    &W[(size_t)(kt + bkr + (p << 3)) * N + bn + bc4]);
        }
        // ---- compute current stage ----
        #pragma unroll 4
        for (int k = 0; k < 32; k++) {
            const float4* a4 = reinterpret_cast<const float4*>(As[cur][k]);
            const float4* b4 = reinterpret_cast<const float4*>(Bs[cur][k]);
            float4 a0 = a4[(ty << 1)],     a1 = a4[(ty << 1) + 1];
            float4 b0 = b4[(tx << 1)],     b1 = b4[(tx << 1) + 1];
            float av[8] = {a0.x, a0.y, a0.z, a0.w, a1.x, a1.y, a1.z, a1.w};
            float bv[8] = {b0.x, b0.y, b0.z, b0.w, b1.x, b1.y, b1.z, b1.w};
            #pragma unroll
            for (int i = 0; i < 8; i++)
                #pragma unroll
                for (int j = 0; j < 8; j++)
                    acc[i][j] = fmaf(av[i], bv[j], acc[i][j]);
        }
        if (t + 1 < nt) {
            #pragma unroll
            for (int j = 0; j < 8; j++) {
                As[nxt][(j << 2) + 0][tid] = ar[j].x;
                As[nxt][(j << 2) + 1][tid] = ar[j].y;
                As[nxt][(j << 2) + 2][tid] = ar[j].z;
                As[nxt][(j << 2) + 3][tid] = ar[j].w;
            }
            #pragma unroll
            for (int p = 0; p < 4; p++)
                *reinterpret_cast<float4*>(&Bs[nxt][bkr + (p << 3)][bc4]) = br[p];
            __syncthreads();
        }
    }

    // ---- epilogue ----
    int col = bn + (tx << 3);
    float4 bi0 = *reinterpret_cast<const float4*>(&bias[col]);
    float4 bi1 = *reinterpret_cast<const float4*>(&bias[col + 4]);
    #pragma unroll
    for (int i = 0; i < 8; i++) {
        int row = bm + (ty << 3) + i;
        float4 c0, c1;
        c0.x = acc[i][0] + bi0.x; c0.y = acc[i][1] + bi0.y;
        c0.z = acc[i][2] + bi0.z; c0.w = acc[i][3] + bi0.w;
        c1.x = acc[i][4] + bi1.x; c1.y = acc[i][5] + bi1.y;
        c1.z = acc[i][6] + bi1.z; c1.w = acc[i][7] + bi1.w;
        if (EPI == 1) {
            float4 r0 = *reinterpret_cast<const float4*>(&R[(size_t)row * N + col]);
            float4 r1 = *reinterpret_cast<const float4*>(&R[(size_t)row * N + col + 4]);
            c0.x += r0.x; c0.y += r0.y; c0.z += r0.z; c0.w += r0.w;
            c1.x += r1.x; c1.y += r1.y; c1.z += r1.z; c1.w += r1.w;
        }
        if (EPI == 2) {
            c0.x = fmaxf(c0.x, 0.0f); c0.y = fmaxf(c0.y, 0.0f);
            c0.z = fmaxf(c0.z, 0.0f); c0.w = fmaxf(c0.w, 0.0f);
            c1.x = fmaxf(c1.x, 0.0f); c1.y = fmaxf(c1.y, 0.0f);
            c1.z = fmaxf(c1.z, 0.0f); c1.w = fmaxf(c1.w, 0.0f);
        }
        *reinterpret_cast<float4*>(&C[(size_t)row * N + col])     = c0;
        *reinterpret_cast<float4*>(&C[(size_t)row * N + col + 4]) = c1;
    }
}

template<int EPI>
__global__ __launch_bounds__(128) void sgemm_kernel(
    const float* __restrict__ A, const float* __restrict__ W,
    const float* __restrict__ bias, const float* __restrict__ R,
    float* __restrict__ C, int N, int K)
{
    gemm_tile<EPI>(A, W, bias, R, C, N, K);
}

// Fused Q/K/V projection: gridDim.z = 3 selects the matrix. Q reads Aq;
// K and V read Akv (equals Aq for self-attn, vq_output for cross-attn).
__global__ __launch_bounds__(128) void sgemm_qkv_kernel(
    const float* __restrict__ Aq, const float* __restrict__ Akv,
    const float* __restrict__ W, const float* __restrict__ bias,
    float* __restrict__ C)
{
    int z = blockIdx.z;
    gemm_tile<0>((z == 0) ? Aq : Akv, W + (size_t)z * DD, bias + z * D_MODEL,
                 nullptr, C + (size_t)z * MD, D_MODEL, D_MODEL);
}

// ------------------------- attention: scores = Qh @ Kh^T * 0.125 -------------
__global__ __launch_bounds__(256) void attn_scores_kernel(
    const float* __restrict__ Q, const float* __restrict__ Km, float* __restrict__ P)
{
    __shared__ float Qs[64][68];   // [kdim][qrow]
    __shared__ float Ks[64][68];   // [kdim][krow]
    int bh = blockIdx.z;
    int b = bh >> 4, h = bh & 15;
    int q0 = blockIdx.y << 6, k0 = blockIdx.x << 6;
    int tid = threadIdx.x;
    int lrow = tid >> 2;
    int lk0  = (tid & 3) << 4;
    const float* qb = Q + (size_t)(b * SEQ + q0 + lrow) * D_MODEL + h * DK + lk0;
    const float* kb = Km + (size_t)(b * SEQ + k0 + lrow) * D_MODEL + h * DK + lk0;
    #pragma unroll
    for (int u = 0; u < 4; u++) {
        float4 qv = *reinterpret_cast<const float4*>(qb + (u << 2));
        float4 kv = *reinterpret_cast<const float4*>(kb + (u << 2));
        int kd = lk0 + (u << 2);
        Qs[kd+0][lrow]=qv.x; Qs[kd+1][lrow]=qv.y; Qs[kd+2][lrow]=qv.z; Qs[kd+3][lrow]=qv.w;
        Ks[kd+0][lrow]=kv.x; Ks[kd+1][lrow]=kv.y; Ks[kd+2][lrow]=kv.z; Ks[kd+3][lrow]=kv.w;
    }
    __syncthreads();
    int tx = tid & 15, ty = tid >> 4;
    float acc[4][4];
    #pragma unroll
    for (int i = 0; i < 4; i++)
        #pragma unroll
        for (int j = 0; j < 4; j++) acc[i][j] = 0.0f;
    #pragma unroll 8
    for (int k = 0; k < 64; k++) {
        float4 a = *reinterpret_cast<const float4*>(&Qs[k][ty << 2]);
        float4 bb = *reinterpret_cast<const float4*>(&Ks[k][tx << 2]);
        float av[4] = {a.x, a.y, a.z, a.w};
        float bv[4] = {bb.x, bb.y, bb.z, bb.w};
        #pragma unroll
        for (int i = 0; i < 4; i++)
            #pragma unroll
            for (int j = 0; j < 4; j++)
                acc[i][j] = fmaf(av[i], bv[j], acc[i][j]);
    }
    #pragma unroll
    for (int i = 0; i < 4; i++) {
        float4 r;
        r.x = acc[i][0] * 0.125f; r.y = acc[i][1] * 0.125f;
        r.z = acc[i][2] * 0.125f; r.w = acc[i][3] * 0.125f;
        *reinterpret_cast<float4*>(
            &P[((size_t)bh * SEQ + q0 + (ty << 2) + i) * SEQ + k0 + (tx << 2)]) = r;
    }
}

// ------------------------- softmax (rows of 512) ------------------------------
__global__ __launch_bounds__(128) void softmax_kernel(float* __restrict__ P) {
    __shared__ float sh[4];
    size_t row = blockIdx.x;
    float* p = P + row * SEQ;
    int tid = threadIdx.x;
    float v0 = p[tid], v1 = p[tid + 128], v2 = p[tid + 256], v3 = p[tid + 384];
    float m = fmaxf(fmaxf(v0, v1), fmaxf(v2, v3));
    m = warp_max(m);
    if ((tid & 31) == 0) sh[tid >> 5] = m;
    __syncthreads();
    float mm = fmaxf(fmaxf(sh[0], sh[1]), fmaxf(sh[2], sh[3]));
    v0 = expf(v0 - mm); v1 = expf(v1 - mm); v2 = expf(v2 - mm); v3 = expf(v3 - mm);
    float s = v0 + v1 + v2 + v3;
    s = warp_sum(s);
    __syncthreads();
    if ((tid & 31) == 0) sh[tid >> 5] = s;
    __syncthreads();
    float inv = 1.0f / (sh[0] + sh[1] + sh[2] + sh[3]);
    p[tid] = v0 * inv; p[tid + 128] = v1 * inv; p[tid + 256] = v2 * inv; p[tid + 384] = v3 * inv;
}

// ------------------------- attention: O = P @ Vh ------------------------------
__global__ __launch_bounds__(256) void attn_av_kernel(
    const float* __restrict__ P, const float* __restrict__ V, float* __restrict__ O)
{
    __shared__ float Ps[64][68];   // [krow][qrow]
    __shared__ float Vs[64][68];   // [krow][dim]
    int bh = blockIdx.z;
    int b = bh >> 4, h = bh & 15;
    int q0 = blockIdx.y << 6;
    int tid = threadIdx.x;
    int lrow = tid >> 2;
    int lc0  = (tid & 3) << 4;
    int tx = tid & 15, ty = tid >> 4;
    float acc[4][4];
    #pragma unroll
    for (int i = 0; i < 4; i++)
        #pragma unroll
        for (int j = 0; j < 4; j++) acc[i][j] = 0.0f;

    for (int kt = 0; kt < SEQ; kt += 64) {
        const float* pb = P + ((size_t)bh * SEQ + q0 + lrow) * SEQ + kt + lc0;
        const float* vb = V + (size_t)(b * SEQ + kt + lrow) * D_MODEL + h * DK + lc0;
        #pragma unroll
        for (int u = 0; u < 4; u++) {
            float4 pv = *reinterpret_cast<const float4*>(pb + (u << 2));
            int kc = lc0 + (u << 2);
            Ps[kc+0][lrow]=pv.x; Ps[kc+1][lrow]=pv.y; Ps[kc+2][lrow]=pv.z; Ps[kc+3][lrow]=pv.w;
            float4 vv = *reinterpret_cast<const float4*>(vb + (u << 2));
            *reinterpret_cast<float4*>(&Vs[lrow][lc0 + (u << 2)]) = vv;
        }
        __syncthreads();
        #pragma unroll 8
        for (int k = 0; k < 64; k++) {
            float4 a = *reinterpret_cast<const float4*>(&Ps[k][ty << 2]);
            float4 bb = *reinterpret_cast<const float4*>(&Vs[k][tx << 2]);
            float av[4] = {a.x, a.y, a.z, a.w};
            float bv[4] = {bb.x, bb.y, bb.z, bb.w};
            #pragma unroll
            for (int i = 0; i < 4; i++)
                #pragma unroll
                for (int j = 0; j < 4; j++)
                    acc[i][j] = fmaf(av[i], bv[j], acc[i][j]);
        }
        __syncthreads();
    }
    #pragma unroll
    for (int i = 0; i < 4; i++) {
        float4 r = make_float4(acc[i][0], acc[i][1], acc[i][2], acc[i][3]);
        *reinterpret_cast<float4*>(
            &O[(size_t)(b * SEQ + q0 + (ty << 2) + i) * D_MODEL + h * DK + (tx << 2)]) = r;
    }
}

// ------------------------- VQ -------------------------------------------------
__global__ void enorm_kernel(const float* __restrict__ emb, float* __restrict__ en) {
    int j = blockIdx.x * blockDim.x + threadIdx.x;
    if (j < VQN) {
        float s = 0.0f;
        #pragma unroll 16
        for (int t = 0; t < VQD; t++) { float e = emb[j * VQD + t]; s = fmaf(e, e, s); }
        en[j] = s;
    }
}

__global__ __launch_bounds__(128) void vq_kernel(
    const float* __restrict__ E, const float* __restrict__ emb,
    const float* __restrict__ en, float* __restrict__ VQ, float* __restrict__ err)
{
    __shared__ float f[VQD];
    __shared__ float sval[128];
    __shared__ int   sidx[128];
    int row = blockIdx.x;
    int chunk = row % VQCHUNKS;
    int bd = row / VQCHUNKS;
    int d = bd % D_MODEL, b = bd / D_MODEL;
    int s0 = chunk * VQD;
    int tid = threadIdx.x;
    if (tid < VQD) f[tid] = E[(size_t)(b * SEQ + s0 + tid) * D_MODEL + d];
    __syncthreads();

    float best = INFINITY; int bidx = 0x7fffffff;
    for (int j = tid; j < VQN; j += 128) {
        const float* e = emb + (size_t)j * VQD;
        float dot = 0.0f;
        #pragma unroll 16
        for (int t = 0; t < VQD; t++) dot = fmaf(f[t], e[t], dot);
        float dist = en[j] - 2.0f * dot;     // + ||f||^2 constant: argmin-equivalent
        if (dist < best) { best = dist; bidx = j; }
    }
    sval[tid] = best; sidx[tid] = bidx;
    __syncthreads();
    #pragma unroll
    for (int s = 64; s > 0; s >>= 1) {
        if (tid < s) {
            float ov = sval[tid + s]; int oi = sidx[tid + s];
            if (ov < sval[tid] || (ov == sval[tid] && oi < sidx[tid])) {
                sval[tid] = ov; sidx[tid] = oi;
            }
        }
        __syncthreads();
    }
    int win = sidx[0];
    if (tid < VQD) {
        float e = emb[(size_t)win * VQD + tid];
        VQ[(size_t)(b * SEQ + s0 + tid) * D_MODEL + d] = e;
        float df = e - f[tid];
        float s2 = warp_sum(df * df);
        if ((tid & 31) == 0) sval[tid >> 5] = s2;
    }
    __syncthreads();
    if (tid == 0) err[row] = sval[0] + sval[1];
}

__global__ void loss_kernel(const float* __restrict__ err, float* __restrict__ out) {
    __shared__ float sh[8];
    int tid = threadIdx.x;
    float s = 0.0f;
    for (int i = tid; i < VQROWS; i += 256) s += err[i];
    s = warp_sum(s);
    if ((tid & 31) == 0) sh[tid >> 5] = s;
    __syncthreads();
    if (tid == 0) {
        float tot = sh[0]+sh[1]+sh[2]+sh[3]+sh[4]+sh[5]+sh[6]+sh[7];
        out[0] = 0.25f * tot / (float)(BATCH * D_MODEL * SEQ);
    }
}

// ------------------------- host-side orchestration ----------------------------
struct Scratch {
    float *x, *x2, *qkv, *o, *ff, *attn, *enorm, *vqerr;
};
static Scratch get_scratch() {
    static Scratch s;
    static bool init = false;
    if (!init) {
        cudaGetSymbolAddress((void**)&s.x,     g_x);
        cudaGetSymbolAddress((void**)&s.x2,    g_x2);
        cudaGetSymbolAddress((void**)&s.qkv,   g_qkv);
        cudaGetSymbolAddress((void**)&s.o,     g_o);
        cudaGetSymbolAddress((void**)&s.ff,    g_ff);
        cudaGetSymbolAddress((void**)&s.attn,  g_attn);
        cudaGetSymbolAddress((void**)&s.enorm, g_enorm);
        cudaGetSymbolAddress((void**)&s.vqerr, g_vqerr);
        init = true;
    }
    return s;
}

static void launch_gemm(int epi, const float* A, const float* W, const float* bias,
                        const float* R, float* C, int N, int K)
{
    dim3 grid(N / 64, MTOK / 128), block(128);
    if (epi == 0)      sgemm_kernel<0><<<grid, block>>>(A, W, bias, R, C, N, K);
    else if (epi == 1) sgemm_kernel<1><<<grid, block>>>(A, W, bias, R, C, N, K);
    else               sgemm_kernel<2><<<grid, block>>>(A, W, bias, R, C, N, K);
}

static void run_mha(const float* xq, const float* xkv, const float* w, const float* bias,
                    float* xres, const Scratch& s)
{
    const float* q = s.qkv;
    const float* k = s.qkv + MD;
    const float* v = s.qkv + 2 * MD;
    sgemm_qkv_kernel<<<dim3(D_MODEL/64, MTOK/128, 3), 128>>>(xq, xkv, w, bias, s.qkv);
    attn_scores_kernel<<<dim3(SEQ/64, SEQ/64, BATCH*NHEAD), 256>>>(q, k, s.attn);
    softmax_kernel<<<BATCH*NHEAD*SEQ, 128>>>(s.attn);
    attn_av_kernel<<<dim3(1, SEQ/64, BATCH*NHEAD), 256>>>(s.attn, v, s.o);
    launch_gemm(1, s.o, w + 3*DD, bias + 3*D_MODEL, xres, xres, D_MODEL, D_MODEL);
}

extern "C" void kernel_launch(void* const* d_in, const int* in_sizes, int n_in,
                              void* d_out, int out_size)
{
    const float* src        = (const float*)d_in[0];
    const float* trg        = (const float*)d_in[1];
    const float* enc_ln     = (const float*)d_in[2];
    const float* enc_attn_w = (const float*)d_in[3];
    const float* enc_attn_b = (const float*)d_in[4];
    const float* enc_ff_w1  = (const float*)d_in[5];
    const float* enc_ff_b1  = (const float*)d_in[6];
    const float* enc_ff_w2  = (const float*)d_in[7];
    const float* enc_ff_b2  = (const float*)d_in[8];
    const float* enc_fnorm  = (const float*)d_in[9];
    const float* dec_ln     = (const float*)d_in[10];
    const float* dec_a1_w   = (const float*)d_in[11];
    const float* dec_a1_b   = (const float*)d_in[12];
    const float* dec_a2_w   = (const float*)d_in[13];
    const float* dec_a2_b   = (const float*)d_in[14];
    const float* dec_ff_w1  = (const float*)d_in[15];
    const float* dec_ff_b1  = (const float*)d_in[16];
    const float* dec_ff_w2  = (const float*)d_in[17];
    const float* dec_ff_b2  = (const float*)d_in[18];
    const float* dec_fnorm  = (const float*)d_in[19];
    const float* out_w      = (const float*)d_in[20];
    const float* out_b      = (const float*)d_in[21];
    const float* vq_emb     = (const float*)d_in[22];

    float* out      = (float*)d_out;
    float* out_main = out;
    float* out_e    = out + MD;
    float* out_vq   = out + 2 * MD;
    float* out_loss = out + 3 * MD;

    Scratch s = get_scratch();

    // ---------------- encoder ----------------
    copy_kernel<<<MTOK * D_MODEL / (256 * 4), 256>>>(src, s.x);
    for (int l = 0; l < NLAYER; l++) {
        layernorm_kernel<<<MTOK, 256>>>(s.x, s.x2, enc_ln + (size_t)((l*2 + 0) * 2) * D_MODEL);
        run_mha(s.x2, s.x2, enc_attn_w + (size_t)l*4*DD, enc_attn_b + (size_t)l*4*D_MODEL,
                s.x, s);
        layernorm_kernel<<<MTOK, 256>>>(s.x, s.x2, enc_ln + (size_t)((l*2 + 1) * 2) * D_MODEL);
        launch_gemm(2, s.x2, enc_ff_w1 + (size_t)l*D_MODEL*DFF, enc_ff_b1 + (size_t)l*DFF,
                    nullptr, s.ff, DFF, D_MODEL);
        launch_gemm(1, s.ff, enc_ff_w2 + (size_t)l*DFF*D_MODEL, enc_ff_b2 + (size_t)l*D_MODEL,
                    s.x, s.x, D_MODEL, DFF);
    }
    layernorm_kernel<<<MTOK, 256>>>(s.x, out_e, enc_fnorm);

    // ---------------- VQ ----------------
    enorm_kernel<<<(VQN + 127) / 128, 128>>>(vq_emb, s.enorm);
    vq_kernel<<<VQROWS, 128>>>(out_e, vq_emb, s.enorm, out_vq, s.vqerr);
    loss_kernel<<<1, 256>>>(s.vqerr, out_loss);

    // ---------------- decoder ----------------
    copy_kernel<<<MTOK * D_MODEL / (256 * 4), 256>>>(trg, s.x);
    for (int l = 0; l < NLAYER; l++) {
        layernorm_kernel<<<MTOK, 256>>>(s.x, s.x2, dec_ln + (size_t)((l*3 + 0) * 2) * D_MODEL);
        run_mha(s.x2, s.x2, dec_a1_w + (size_t)l*4*DD, dec_a1_b + (size_t)l*4*D_MODEL,
                s.x, s);
        layernorm_kernel<<<MTOK, 256>>>(s.x, s.x2, dec_ln + (size_t)((l*3 + 1) * 2) * D_MODEL);
        run_mha(s.x2, out_vq, dec_a2_w + (size_t)l*4*DD, dec_a2_b + (size_t)l*4*D_MODEL,
                s.x, s);
        layernorm_kernel<<<MTOK, 256>>>(s.x, s.x2, dec_ln + (size_t)((l*3 + 2) * 2) * D_MODEL);
        launch_gemm(2, s.x2, dec_ff_w1 + (size_t)l*D_MODEL*DFF, dec_ff_b1 + (size_t)l*DFF,
                    nullptr, s.ff, DFF, D_MODEL);
        launch_gemm(1, s.ff, dec_ff_w2 + (size_t)l*DFF*D_MODEL, dec_ff_b2 + (size_t)l*D_MODEL,
                    s.x, s.x, D_MODEL, DFF);
    }
    layernorm_kernel<<<MTOK, 256>>>(s.x, s.x2, dec_fnorm);
    launch_gemm(0, s.x2, out_w, out_b, nullptr, out_main, D_MODEL, D_MODEL);
}